// round 14
// baseline (speedup 1.0000x reference)
#include <cuda_runtime.h>
#include <cuda_bf16.h>
#include <math.h>
#include <stdint.h>

// NT-Xent loss via symmetric-triangle INT8 IMMA GEMM. N=4096, D=256, 2N=8192.
// z' = z/||z|| * sqrt(10*log2e); per-row int8 quant: q = rint(z'*127/m_row),
// s_row = m_row/127  =>  sim_ij(log2 domain) = s_i*s_j*(q_i.q_j)  (dot exact s32).
// loss_i = ln2*( lg2(sum_{j!=i} ex2(sim_ij)) - sim_pos );  out = mean.
// 128x64 tiles, triangle (J>=2I), 2 CTAs/SM, double-buffered B prefetch.

#define NN 8192
#define HN 4096
#define DD 256
#define NBI 64                      // 128-row blocks
#define NBJ 128                     // 64-col blocks
#define NFLAT 4160                  // sum_I (128-2I)
#define NRUN 296                    // balanced runs: 16x15 + 280x14
#define C_SCALE 3.7982825615419297f // sqrt(10 * log2(e))
#define LN2 0.6931471805599453f

// ---- device scratch (zero-init; unwritten slots stay 0 -> deterministic) ----
__device__ __align__(512) int8_t g_q[NN * DD];     // quantized z' (2 MB)
__device__ float g_srow[NN];                        // per-row scale
__device__ float g_rowPartW[NFLAT * 256];   // [tile][wx plane 0/1][128 rows]
__device__ float g_colPartW[NFLAT * 256];   // [tile][wy plane 0..3][64 cols]
__device__ float g_posacc[NN];
__device__ float g_lossPartial[32];
__device__ int   g_ctr = 0;

// ---------------------------------------------------------------------------
__device__ __forceinline__ uint32_t smem_u32(const void* p) {
    uint32_t a;
    asm("{ .reg .u64 t; cvta.to.shared.u64 t, %1; cvt.u32.u64 %0, t; }" : "=r"(a) : "l"(p));
    return a;
}
__device__ __forceinline__ void cp16(uint32_t smem_dst, const void* gsrc) {
    asm volatile("cp.async.cg.shared.global [%0], [%1], 16;" :: "r"(smem_dst), "l"(gsrc));
}
#define CP_COMMIT() asm volatile("cp.async.commit_group;" ::: "memory")
#define CP_WAIT0()  asm volatile("cp.async.wait_group 0;" ::: "memory")

__device__ __forceinline__ float ex2f(float x) {
    float y; asm("ex2.approx.f32 %0, %1;" : "=f"(y) : "f"(x)); return y;
}
__device__ __forceinline__ float lg2f(float x) {
    float y; asm("lg2.approx.f32 %0, %1;" : "=f"(y) : "f"(x)); return y;
}
__device__ __forceinline__ void ldsm_x4(uint32_t& r0, uint32_t& r1, uint32_t& r2,
                                        uint32_t& r3, uint32_t addr) {
    asm volatile("ldmatrix.sync.aligned.m8n8.x4.shared.b16 {%0,%1,%2,%3}, [%4];"
                 : "=r"(r0), "=r"(r1), "=r"(r2), "=r"(r3) : "r"(addr));
}
__device__ __forceinline__ void mma16832(int* c, const uint32_t* a, const uint32_t* b) {
    asm volatile(
        "mma.sync.aligned.m16n8k32.row.col.s32.s8.s8.s32 "
        "{%0,%1,%2,%3}, {%4,%5,%6,%7}, {%8,%9}, {%0,%1,%2,%3};"
        : "+r"(c[0]), "+r"(c[1]), "+r"(c[2]), "+r"(c[3])
        : "r"(a[0]), "r"(a[1]), "r"(a[2]), "r"(a[3]), "r"(b[0]), "r"(b[1]));
}

// ---------------------------------------------------------------------------
// Kernel A: normalize, scale by sqrt(10*log2e), per-row int8 quantize.
// Warp per row.
// ---------------------------------------------------------------------------
__global__ __launch_bounds__(256) void normalize_kernel(
    const float* __restrict__ z1, const float* __restrict__ z2)
{
    const int wid = threadIdx.x >> 5, lid = threadIdx.x & 31;
    const int row = blockIdx.x * 8 + wid;
    const float* src = (row < HN) ? (z1 + (size_t)row * DD)
                                  : (z2 + (size_t)(row - HN) * DD);
    float4 v0 = reinterpret_cast<const float4*>(src)[lid];
    float4 v1 = reinterpret_cast<const float4*>(src)[lid + 32];
    float ss = v0.x * v0.x + v0.y * v0.y + v0.z * v0.z + v0.w * v0.w
             + v1.x * v1.x + v1.y * v1.y + v1.z * v1.z + v1.w * v1.w;
    float am = fmaxf(fmaxf(fmaxf(fabsf(v0.x), fabsf(v0.y)), fmaxf(fabsf(v0.z), fabsf(v0.w))),
                     fmaxf(fmaxf(fabsf(v1.x), fabsf(v1.y)), fmaxf(fabsf(v1.z), fabsf(v1.w))));
    #pragma unroll
    for (int off = 16; off > 0; off >>= 1) {
        ss += __shfl_xor_sync(0xffffffffu, ss, off);
        am = fmaxf(am, __shfl_xor_sync(0xffffffffu, am, off));
    }
    float s = C_SCALE / fmaxf(sqrtf(ss), 1e-12f);
    float m = am * s;                       // max |z'| in this row (> 0)
    float f = 127.0f / m * s;               // float -> int8 code scale
    if (lid == 0) g_srow[row] = m * (1.0f / 127.0f);

    int q0 = __float2int_rn(v0.x * f), q1 = __float2int_rn(v0.y * f);
    int q2 = __float2int_rn(v0.z * f), q3 = __float2int_rn(v0.w * f);
    int q4 = __float2int_rn(v1.x * f), q5 = __float2int_rn(v1.y * f);
    int q6 = __float2int_rn(v1.z * f), q7 = __float2int_rn(v1.w * f);
    uint32_t p0 = (uint32_t)(q0 & 255) | ((uint32_t)(q1 & 255) << 8)
                | ((uint32_t)(q2 & 255) << 16) | ((uint32_t)q3 << 24);
    uint32_t p1 = (uint32_t)(q4 & 255) | ((uint32_t)(q5 & 255) << 8)
                | ((uint32_t)(q6 & 255) << 16) | ((uint32_t)q7 << 24);
    uint32_t* dst = reinterpret_cast<uint32_t*>(g_q + (size_t)row * DD);
    dst[lid] = p0;
    dst[32 + lid] = p1;
}

// ---------------------------------------------------------------------------
// Kernel B: triangle 128x64 int8 tiles, 2 CTAs/SM, double-buffered B.
// 256 threads, warp grid 4(m)x2(n), warp tile 32x32, 8 k32-steps.
// SMEM: A 32KB + B 2x16KB = 64KB/CTA.
// ---------------------------------------------------------------------------
__global__ __launch_bounds__(256, 2) void sim_mma_kernel()
{
    extern __shared__ char smem[];
    const uint32_t sb = smem_u32(smem);
    const uint32_t A_BASE = sb, B_BASE = sb + 32768, BSZ = 16384;

    const int tid = threadIdx.x, wid = tid >> 5, lid = tid & 31;
    const int wy = wid >> 1, wx = wid & 1;       // warp grid 4 (m) x 2 (n)
    const int my = wy * 32, nx = wx * 32;

    // balanced run: CTA c gets tiles [f0, f0+len)
    const int c   = blockIdx.x;
    const int len = 14 + (c < 16);
    const int f0  = 14 * c + (c < 16 ? c : 16);

    int I = 0, S = 0;
    while (S + (2 * (NBI - I)) <= f0) { S += 2 * (NBI - I); ++I; }
    int J = 2 * I + (f0 - S);

    const int sub = lid >> 3, lr = lid & 7;
    const int rowA0 = my + ((sub & 1) << 3) + lr;
    const int cAoff = sub >> 1;
    const int rowB0 = nx + ((sub >> 1) << 3) + lr;
    const int cBoff = sub & 1;

    int curI = -1, bufc = 0;
    bool pref = false;
    float re[4] = {0.f, 0.f, 0.f, 0.f};   // segment row sums
    float sr[2][2];                        // per-segment row scales

    for (int t = 0; t < len; ++t) {
        if (!pref) {
            if (t) __syncthreads();
            if (I != curI) {
                for (int i = tid; i < 2048; i += 256) {     // A: 128 rows x 16 chunks
                    int r = i >> 4, cc = i & 15;
                    cp16(A_BASE + r * 256 + ((cc ^ (r & 7)) << 4),
                         &g_q[(size_t)(I * 128 + r) * DD + cc * 16]);
                }
                curI = I;
                #pragma unroll
                for (int i = 0; i < 2; ++i) {
                    int rl = I * 128 + my + 16 * i + (lid >> 2);
                    sr[i][0] = g_srow[rl];
                    sr[i][1] = g_srow[rl + 8];
                }
            }
            for (int i = tid; i < 1024; i += 256) {         // B: 64 rows x 16 chunks
                int r = i >> 4, cc = i & 15;
                cp16(B_BASE + bufc * BSZ + r * 256 + ((cc ^ (r & 7)) << 4),
                     &g_q[(size_t)(J * 64 + r) * DD + cc * 16]);
            }
            CP_COMMIT();
        }
        CP_WAIT0();
        __syncthreads();

        // prefetch next B into the other buffer (window = whole current tile)
        int nI = I, nJ = J + 1;
        if (nJ == NBJ) { ++nI; nJ = 2 * nI; }
        const bool prefNext = (t + 1 < len && nI == I);
        if (prefNext) {
            for (int i = tid; i < 1024; i += 256) {
                int r = i >> 4, cc = i & 15;
                cp16(B_BASE + (bufc ^ 1) * BSZ + r * 256 + ((cc ^ (r & 7)) << 4),
                     &g_q[(size_t)(nJ * 64 + r) * DD + cc * 16]);
            }
            CP_COMMIT();
        }

        // ---- GEMM 128x64x256 int8 (8 k32 steps) ----
        const uint32_t Bb = B_BASE + bufc * BSZ;
        int acc[2][4][4];
        #pragma unroll
        for (int i = 0; i < 2; ++i)
            #pragma unroll
            for (int j = 0; j < 4; ++j)
                #pragma unroll
                for (int q = 0; q < 4; ++q) acc[i][j][q] = 0;

        #pragma unroll
        for (int ks = 0; ks < 8; ++ks) {
            const int c0 = 2 * ks;
            uint32_t a[2][4], b[4][2];
            #pragma unroll
            for (int i = 0; i < 2; ++i) {
                int row = rowA0 + 16 * i;
                ldsm_x4(a[i][0], a[i][1], a[i][2], a[i][3],
                        A_BASE + row * 256 + (((c0 + cAoff) ^ (row & 7)) << 4));
            }
            #pragma unroll
            for (int jj = 0; jj < 2; ++jj) {
                int row = rowB0 + 16 * jj;
                ldsm_x4(b[2 * jj][0], b[2 * jj][1], b[2 * jj + 1][0], b[2 * jj + 1][1],
                        Bb + row * 256 + (((c0 + cBoff) ^ (row & 7)) << 4));
            }
            #pragma unroll
            for (int i = 0; i < 2; ++i)
                #pragma unroll
                for (int j = 0; j < 4; ++j)
                    mma16832(acc[i][j], a[i], b[j]);
        }

        // ---- epilogue (scaled to log2 domain) ----
        const int d = J - 2 * I;
        const int f = f0 + t;
        const int colT = J * 64 + nx + 2 * (lid & 3);
        float sc[4][2];
        #pragma unroll
        for (int j = 0; j < 4; ++j) {
            sc[j][0] = g_srow[colT + 8 * j];
            sc[j][1] = g_srow[colT + 8 * j + 1];
        }

        if (d <= 1) {
            // band tile: cols within own 128-row block. Row sums only, skip r==c.
            #pragma unroll
            for (int i = 0; i < 2; ++i) {
                const int gr0 = I * 128 + my + 16 * i + (lid >> 2);
                const int gr1 = gr0 + 8;
                #pragma unroll
                for (int j = 0; j < 4; ++j) {
                    const int gc0 = colT + 8 * j, gc1 = gc0 + 1;
                    float v0 = __int2float_rn(acc[i][j][0]) * (sr[i][0] * sc[j][0]);
                    float v1 = __int2float_rn(acc[i][j][1]) * (sr[i][0] * sc[j][1]);
                    float v2 = __int2float_rn(acc[i][j][2]) * (sr[i][1] * sc[j][0]);
                    float v3 = __int2float_rn(acc[i][j][3]) * (sr[i][1] * sc[j][1]);
                    if (gc0 != gr0) re[2 * i]     += ex2f(v0);
                    if (gc1 != gr0) re[2 * i]     += ex2f(v1);
                    if (gc0 != gr1) re[2 * i + 1] += ex2f(v2);
                    if (gc1 != gr1) re[2 * i + 1] += ex2f(v3);
                }
            }
        } else {
            float cs[8];
            #pragma unroll
            for (int k = 0; k < 8; ++k) cs[k] = 0.f;
            const bool postl = (d == 64 || d == 65);
            #pragma unroll
            for (int i = 0; i < 2; ++i) {
                const int gr0 = I * 128 + my + 16 * i + (lid >> 2);
                const int gr1 = gr0 + 8;
                #pragma unroll
                for (int j = 0; j < 4; ++j) {
                    float v0 = __int2float_rn(acc[i][j][0]) * (sr[i][0] * sc[j][0]);
                    float v1 = __int2float_rn(acc[i][j][1]) * (sr[i][0] * sc[j][1]);
                    float v2 = __int2float_rn(acc[i][j][2]) * (sr[i][1] * sc[j][0]);
                    float v3 = __int2float_rn(acc[i][j][3]) * (sr[i][1] * sc[j][1]);
                    if (postl) {
                        const int gc0 = colT + 8 * j, gc1 = gc0 + 1;
                        const int p0 = gr0 + HN, p1 = gr1 + HN;
                        if (gc0 == p0) { g_posacc[gr0] = v0; g_posacc[p0] = v0; }
                        if (gc1 == p0) { g_posacc[gr0] = v1; g_posacc[p0] = v1; }
                        if (gc0 == p1) { g_posacc[gr1] = v2; g_posacc[p1] = v2; }
                        if (gc1 == p1) { g_posacc[gr1] = v3; g_posacc[p1] = v3; }
                    }
                    float e0 = ex2f(v0), e1 = ex2f(v1), e2 = ex2f(v2), e3 = ex2f(v3);
                    re[2 * i]     += e0 + e1;
                    re[2 * i + 1] += e2 + e3;
                    cs[2 * j]     += e0 + e2;
                    cs[2 * j + 1] += e1 + e3;
                }
            }
            #pragma unroll
            for (int k = 0; k < 8; ++k) {
                cs[k] += __shfl_xor_sync(0xffffffffu, cs[k], 4);
                cs[k] += __shfl_xor_sync(0xffffffffu, cs[k], 8);
                cs[k] += __shfl_xor_sync(0xffffffffu, cs[k], 16);
            }
            if (lid < 4) {
                float* dstc = &g_colPartW[(size_t)f * 256 + wy * 64 + nx];
                #pragma unroll
                for (int k = 0; k < 8; ++k)
                    dstc[8 * (k >> 1) + 2 * lid + (k & 1)] = cs[k];
            }
        }

        // segment end (I changes) or run end: flush row sums
        if (nI != I || t == len - 1) {
            float rr[4] = {re[0], re[1], re[2], re[3]};
            #pragma unroll
            for (int e = 0; e < 4; ++e) {
                rr[e] += __shfl_xor_sync(0xffffffffu, rr[e], 1);
                rr[e] += __shfl_xor_sync(0xffffffffu, rr[e], 2);
            }
            if ((lid & 3) == 0) {
                float* dstr = &g_rowPartW[(size_t)f * 256 + wx * 128];
                #pragma unroll
                for (int e = 0; e < 4; ++e) {
                    int rl = my + 16 * (e >> 1) + 8 * (e & 1) + (lid >> 2);
                    dstr[rl] = rr[e];
                }
            }
            #pragma unroll
            for (int e = 0; e < 4; ++e) re[e] = 0.f;
        }

        if (prefNext) bufc ^= 1;
        pref = prefNext;
        I = nI; J = nJ;
    }
}

// ---------------------------------------------------------------------------
// Kernel C: per-row loss + global reduce; last-done block finalizes.
// f(I,J) = I*(129-I) + (J - 2I).
// ---------------------------------------------------------------------------
__global__ __launch_bounds__(256) void loss_reduce_kernel(float* __restrict__ out)
{
    const int r  = blockIdx.x * 256 + threadIdx.x;
    const int Ir = r >> 7, lr = r & 127;

    float tot = 0.f;
    {
        int f = Ir * (129 - Ir);
        const int cnt = NBJ - 2 * Ir;
        for (int k = 0; k < cnt; ++k, ++f) {
            const float* p = &g_rowPartW[(size_t)f * 256];
            tot += p[lr] + p[128 + lr];
        }
    }
    {
        const int Jc = r >> 6, lc = r & 63;
        const int imax = Jc >> 1;
        for (int I2 = 0; I2 <= imax; ++I2) {
            const int f2 = I2 * (129 - I2) + (Jc - 2 * I2);
            const float* p = &g_colPartW[(size_t)f2 * 256];
            tot += (p[lc] + p[64 + lc]) + (p[128 + lc] + p[192 + lc]);
        }
    }
    float loss = lg2f(tot) - g_posacc[r];

    __shared__ float sm[256];
    __shared__ int last;
    sm[threadIdx.x] = loss;
    __syncthreads();
    #pragma unroll
    for (int off = 128; off > 0; off >>= 1) {
        if (threadIdx.x < off) sm[threadIdx.x] += sm[threadIdx.x + off];
        __syncthreads();
    }
    if (threadIdx.x == 0) {
        g_lossPartial[blockIdx.x] = sm[0];
        __threadfence();
        last = (atomicAdd(&g_ctr, 1) == 31);
    }
    __syncthreads();
    if (last && threadIdx.x < 32) {
        __threadfence();
        float v = g_lossPartial[threadIdx.x];
        #pragma unroll
        for (int off = 16; off > 0; off >>= 1)
            v += __shfl_down_sync(0xffffffffu, v, off);
        if (threadIdx.x == 0) { out[0] = v * (LN2 / (float)NN); g_ctr = 0; }
    }
}

// ---------------------------------------------------------------------------
extern "C" void kernel_launch(void* const* d_in, const int* in_sizes, int n_in,
                              void* d_out, int out_size)
{
    (void)in_sizes; (void)n_in; (void)out_size;
    const float* z1 = (const float*)d_in[0];
    const float* z2 = (const float*)d_in[1];
    float* out = (float*)d_out;

    static int smem_set = 0;
    const int SMEM_BYTES = 65536;          // A 32KB + B 2x16KB -> 2 CTAs/SM
    if (!smem_set) {
        cudaFuncSetAttribute(sim_mma_kernel,
                             cudaFuncAttributeMaxDynamicSharedMemorySize, SMEM_BYTES);
        smem_set = 1;
    }

    normalize_kernel<<<NN / 8, 256>>>(z1, z2);
    sim_mma_kernel<<<NRUN, 256, SMEM_BYTES>>>();
    loss_reduce_kernel<<<32, 256>>>(out);
}

// round 16
// speedup vs baseline: 2.3749x; 2.3749x over previous
#include <cuda_runtime.h>
#include <cuda_fp16.h>
#include <math.h>
#include <stdint.h>

// NT-Xent loss via symmetric-triangle HMMA fp16 GEMM (fp16 accumulate).
// N=4096, D=256, 2N=8192. z' = z/||z|| * sqrt(10*log2e) (fp16)
// => acc = sim_ij * log2(e). loss_i = ln2*( lg2(sum_{j!=i} ex2(acc_ij)) - acc_pos ).
// 128x64 tiles, triangle (J>=2I), 2 CTAs/SM; B(t+1) prefetched during epilogue.

#define NN 8192
#define HN 4096
#define DD 256
#define NBI 64                      // 128-row blocks
#define NBJ 128                     // 64-col blocks
#define NFLAT 4160                  // sum_I (128-2I)
#define NRUN 296                    // balanced runs: 16x15 + 280x14
#define C_SCALE 3.7982825615419297f // sqrt(10 * log2(e))
#define LN2 0.6931471805599453f

// ---- device scratch (zero-init; unwritten slots stay 0 -> deterministic) ----
__device__ __align__(512) __half g_zh[NN * DD];    // normalized z, fp16 (4 MB)
__device__ float g_rowPartW[NFLAT * 256];   // [tile][wx plane 0/1][128 rows]
__device__ float g_colPartW[NFLAT * 256];   // [tile][wy plane 0..3][64 cols]
__device__ float g_posacc[NN];
__device__ float g_lossPartial[32];
__device__ int   g_ctr = 0;

// ---------------------------------------------------------------------------
__device__ __forceinline__ uint32_t smem_u32(const void* p) {
    uint32_t a;
    asm("{ .reg .u64 t; cvta.to.shared.u64 t, %1; cvt.u32.u64 %0, t; }" : "=r"(a) : "l"(p));
    return a;
}
__device__ __forceinline__ void cp16(uint32_t smem_dst, const void* gsrc) {
    asm volatile("cp.async.cg.shared.global [%0], [%1], 16;" :: "r"(smem_dst), "l"(gsrc));
}
#define CP_COMMIT() asm volatile("cp.async.commit_group;" ::: "memory")
#define CP_WAIT0()  asm volatile("cp.async.wait_group 0;" ::: "memory")

__device__ __forceinline__ float ex2f(float x) {
    float y; asm("ex2.approx.f32 %0, %1;" : "=f"(y) : "f"(x)); return y;
}
__device__ __forceinline__ float lg2f(float x) {
    float y; asm("lg2.approx.f32 %0, %1;" : "=f"(y) : "f"(x)); return y;
}
__device__ __forceinline__ void ldsm_x4(uint32_t& r0, uint32_t& r1, uint32_t& r2,
                                        uint32_t& r3, uint32_t addr) {
    asm volatile("ldmatrix.sync.aligned.m8n8.x4.shared.b16 {%0,%1,%2,%3}, [%4];"
                 : "=r"(r0), "=r"(r1), "=r"(r2), "=r"(r3) : "r"(addr));
}
// fp16-accumulate HMMA: C fragment = 2 x .f16x2 regs
__device__ __forceinline__ void mma16816h(uint32_t* c, const uint32_t* a, const uint32_t* b) {
    asm volatile(
        "mma.sync.aligned.m16n8k16.row.col.f16.f16.f16.f16 "
        "{%0,%1}, {%2,%3,%4,%5}, {%6,%7}, {%0,%1};"
        : "+r"(c[0]), "+r"(c[1])
        : "r"(a[0]), "r"(a[1]), "r"(a[2]), "r"(a[3]), "r"(b[0]), "r"(b[1]));
}

// ---------------------------------------------------------------------------
// Kernel A: normalize rows, scale by sqrt(10*log2e), emit fp16. Warp per row.
// ---------------------------------------------------------------------------
__global__ __launch_bounds__(256) void normalize_kernel(
    const float* __restrict__ z1, const float* __restrict__ z2)
{
    const int wid = threadIdx.x >> 5, lid = threadIdx.x & 31;
    const int row = blockIdx.x * 8 + wid;
    const float* src = (row < HN) ? (z1 + (size_t)row * DD)
                                  : (z2 + (size_t)(row - HN) * DD);
    float4 v0 = reinterpret_cast<const float4*>(src)[lid];
    float4 v1 = reinterpret_cast<const float4*>(src)[lid + 32];
    float ss = v0.x * v0.x + v0.y * v0.y + v0.z * v0.z + v0.w * v0.w
             + v1.x * v1.x + v1.y * v1.y + v1.z * v1.z + v1.w * v1.w;
    #pragma unroll
    for (int off = 16; off > 0; off >>= 1) ss += __shfl_xor_sync(0xffffffffu, ss, off);
    float s = C_SCALE / fmaxf(sqrtf(ss), 1e-12f);
    __half2* dst = reinterpret_cast<__half2*>(g_zh + (size_t)row * DD);
    dst[2 * lid + 0]      = __floats2half2_rn(v0.x * s, v0.y * s);
    dst[2 * lid + 1]      = __floats2half2_rn(v0.z * s, v0.w * s);
    dst[64 + 2 * lid + 0] = __floats2half2_rn(v1.x * s, v1.y * s);
    dst[64 + 2 * lid + 1] = __floats2half2_rn(v1.z * s, v1.w * s);
}

// ---------------------------------------------------------------------------
// Kernel B: triangle 128x64 tiles, 2 CTAs/SM. 256 threads, warp grid 4(m)x2(n),
// warp tile 32x32. SMEM: A resident 64KB + B single 32KB = 96KB.
// B(t+1) issued right after GEMM(t)'s barrier; epilogue is the prefetch window.
// ---------------------------------------------------------------------------
__global__ __launch_bounds__(256, 2) void sim_mma_kernel()
{
    extern __shared__ char smem[];
    const uint32_t sb = smem_u32(smem);
    const uint32_t A_BASE = sb, B_BASE = sb + 65536;

    const int tid = threadIdx.x, wid = tid >> 5, lid = tid & 31;
    const int wy = wid >> 1, wx = wid & 1;       // warp grid 4 (m) x 2 (n)
    const int my = wy * 32, nx = wx * 32;

    // balanced run: CTA c gets tiles [f0, f0+len)
    const int c   = blockIdx.x;
    const int len = 14 + (c < 16);
    const int f0  = 14 * c + (c < 16 ? c : 16);

    int I = 0, S = 0;
    while (S + (2 * (NBI - I)) <= f0) { S += 2 * (NBI - I); ++I; }
    int J = 2 * I + (f0 - S);

    const int sub = lid >> 3, lr = lid & 7;
    const int rowA0 = my + ((sub & 1) << 3) + lr;
    const int cAoff = sub >> 1;
    const int rowB0 = nx + ((sub >> 1) << 3) + lr;
    const int cBoff = sub & 1;

    int curI = -1;
    float re[4] = {0.f, 0.f, 0.f, 0.f};   // segment row sums

    for (int t = 0; t < len; ++t) {
        if (I != curI) {
            // segment start: load A (128x256) + this tile's B (64x256)
            for (int i = tid; i < 4096; i += 256) {
                int r = i >> 5, cc = i & 31;
                cp16(A_BASE + r * 512 + ((cc ^ (r & 7)) << 4),
                     &g_zh[(size_t)(I * 128 + r) * DD + cc * 8]);
            }
            for (int i = tid; i < 2048; i += 256) {
                int r = i >> 5, cc = i & 31;
                cp16(B_BASE + r * 512 + ((cc ^ (r & 7)) << 4),
                     &g_zh[(size_t)(J * 64 + r) * DD + cc * 8]);
            }
            CP_COMMIT();
            curI = I;
        }
        CP_WAIT0();
        __syncthreads();

        // ---- GEMM 128x64x256 (fp16 accumulate) ----
        uint32_t acc[2][4][2];
        #pragma unroll
        for (int i = 0; i < 2; ++i)
            #pragma unroll
            for (int j = 0; j < 4; ++j) { acc[i][j][0] = 0u; acc[i][j][1] = 0u; }

        #pragma unroll
        for (int ks = 0; ks < 16; ++ks) {
            const int c0 = 2 * ks;
            uint32_t a[2][4], b[4][2];
            #pragma unroll
            for (int i = 0; i < 2; ++i) {
                int row = rowA0 + 16 * i;
                ldsm_x4(a[i][0], a[i][1], a[i][2], a[i][3],
                        A_BASE + row * 512 + (((c0 + cAoff) ^ (row & 7)) << 4));
            }
            #pragma unroll
            for (int jj = 0; jj < 2; ++jj) {
                int row = rowB0 + 16 * jj;
                ldsm_x4(b[2 * jj][0], b[2 * jj][1], b[2 * jj + 1][0], b[2 * jj + 1][1],
                        B_BASE + row * 512 + (((c0 + cBoff) ^ (row & 7)) << 4));
            }
            #pragma unroll
            for (int i = 0; i < 2; ++i)
                #pragma unroll
                for (int j = 0; j < 4; ++j)
                    mma16816h(acc[i][j], a[i], b[j]);
        }
        __syncthreads();                  // all warps done reading B buffer

        // next tile coords; issue B(t+1) if same segment (prefetch window = epilogue)
        int nI = I, nJ = J + 1;
        if (nJ == NBJ) { ++nI; nJ = 2 * nI; }
        if (t + 1 < len && nI == I) {
            for (int i = tid; i < 2048; i += 256) {
                int r = i >> 5, cc = i & 31;
                cp16(B_BASE + r * 512 + ((cc ^ (r & 7)) << 4),
                     &g_zh[(size_t)(nJ * 64 + r) * DD + cc * 8]);
            }
            CP_COMMIT();
        }

        // ---- epilogue ----
        const int d = J - 2 * I;
        const int f = f0 + t;
        if (d <= 1) {
            // band tile: cols within own 128-row block. Row sums only, skip r==c.
            const int colT = J * 64 + nx + 2 * (lid & 3);
            #pragma unroll
            for (int i = 0; i < 2; ++i) {
                const int gr0 = I * 128 + my + 16 * i + (lid >> 2);
                const int gr1 = gr0 + 8;
                #pragma unroll
                for (int j = 0; j < 4; ++j) {
                    const int gc0 = colT + 8 * j, gc1 = gc0 + 1;
                    float2 f01 = __half22float2(*reinterpret_cast<__half2*>(&acc[i][j][0]));
                    float2 f23 = __half22float2(*reinterpret_cast<__half2*>(&acc[i][j][1]));
                    if (gc0 != gr0) re[2 * i]     += ex2f(f01.x);
                    if (gc1 != gr0) re[2 * i]     += ex2f(f01.y);
                    if (gc0 != gr1) re[2 * i + 1] += ex2f(f23.x);
                    if (gc1 != gr1) re[2 * i + 1] += ex2f(f23.y);
                }
            }
        } else {
            if (d == 64 || d == 65) {     // pos tile: cols = rows + 4096
                const int colT = J * 64 + nx + 2 * (lid & 3);
                #pragma unroll
                for (int i = 0; i < 2; ++i) {
                    const int gr0 = I * 128 + my + 16 * i + (lid >> 2);
                    const int gr1 = gr0 + 8;
                    const int p0 = gr0 + HN, p1 = gr1 + HN;
                    #pragma unroll
                    for (int j = 0; j < 4; ++j) {
                        const int gc0 = colT + 8 * j, gc1 = gc0 + 1;
                        float2 f01 = __half22float2(*reinterpret_cast<__half2*>(&acc[i][j][0]));
                        float2 f23 = __half22float2(*reinterpret_cast<__half2*>(&acc[i][j][1]));
                        if (gc0 == p0) { g_posacc[gr0] = f01.x; g_posacc[p0] = f01.x; }
                        if (gc1 == p0) { g_posacc[gr0] = f01.y; g_posacc[p0] = f01.y; }
                        if (gc0 == p1) { g_posacc[gr1] = f23.x; g_posacc[p1] = f23.x; }
                        if (gc1 == p1) { g_posacc[gr1] = f23.y; g_posacc[p1] = f23.y; }
                    }
                }
            }
            float cs[8];
            #pragma unroll
            for (int k = 0; k < 8; ++k) cs[k] = 0.f;
            #pragma unroll
            for (int i = 0; i < 2; ++i)
                #pragma unroll
                for (int j = 0; j < 4; ++j) {
                    float2 f01 = __half22float2(*reinterpret_cast<__half2*>(&acc[i][j][0]));
                    float2 f23 = __half22float2(*reinterpret_cast<__half2*>(&acc[i][j][1]));
                    float e0 = ex2f(f01.x), e1 = ex2f(f01.y);
                    float e2 = ex2f(f23.x), e3 = ex2f(f23.y);
                    re[2 * i]     += e0 + e1;
                    re[2 * i + 1] += e2 + e3;
                    cs[2 * j]     += e0 + e2;
                    cs[2 * j + 1] += e1 + e3;
                }
            #pragma unroll
            for (int k = 0; k < 8; ++k) {
                cs[k] += __shfl_xor_sync(0xffffffffu, cs[k], 4);
                cs[k] += __shfl_xor_sync(0xffffffffu, cs[k], 8);
                cs[k] += __shfl_xor_sync(0xffffffffu, cs[k], 16);
            }
            if (lid < 4) {
                float* dstc = &g_colPartW[(size_t)f * 256 + wy * 64 + nx];
                #pragma unroll
                for (int k = 0; k < 8; ++k)
                    dstc[8 * (k >> 1) + 2 * lid + (k & 1)] = cs[k];
            }
        }

        // segment end (I changes) or run end: flush row sums
        if (nI != I || t == len - 1) {
            float rr[4] = {re[0], re[1], re[2], re[3]};
            #pragma unroll
            for (int e = 0; e < 4; ++e) {
                rr[e] += __shfl_xor_sync(0xffffffffu, rr[e], 1);
                rr[e] += __shfl_xor_sync(0xffffffffu, rr[e], 2);
            }
            if ((lid & 3) == 0) {
                float* dstr = &g_rowPartW[(size_t)f * 256 + wx * 128];
                #pragma unroll
                for (int e = 0; e < 4; ++e) {
                    int rl = my + 16 * (e >> 1) + 8 * (e & 1) + (lid >> 2);
                    dstr[rl] = rr[e];
                }
            }
            #pragma unroll
            for (int e = 0; e < 4; ++e) re[e] = 0.f;
        }

        I = nI; J = nJ;
    }
}

// ---------------------------------------------------------------------------
// Kernel C: per-row loss + global reduce; last-done block finalizes.
// f(I,J) = I*(129-I) + (J - 2I).
// ---------------------------------------------------------------------------
__global__ __launch_bounds__(256) void loss_reduce_kernel(float* __restrict__ out)
{
    const int r  = blockIdx.x * 256 + threadIdx.x;
    const int Ir = r >> 7, lr = r & 127;

    float tot = 0.f;
    {
        int f = Ir * (129 - Ir);
        const int cnt = NBJ - 2 * Ir;
        for (int k = 0; k < cnt; ++k, ++f) {
            const float* p = &g_rowPartW[(size_t)f * 256];
            tot += p[lr] + p[128 + lr];
        }
    }
    {
        const int Jc = r >> 6, lc = r & 63;
        const int imax = Jc >> 1;
        for (int I2 = 0; I2 <= imax; ++I2) {
            const int f2 = I2 * (129 - I2) + (Jc - 2 * I2);
            const float* p = &g_colPartW[(size_t)f2 * 256];
            tot += (p[lc] + p[64 + lc]) + (p[128 + lc] + p[192 + lc]);
        }
    }
    float loss = lg2f(tot) - g_posacc[r];

    __shared__ float sm[256];
    __shared__ int last;
    sm[threadIdx.x] = loss;
    __syncthreads();
    #pragma unroll
    for (int off = 128; off > 0; off >>= 1) {
        if (threadIdx.x < off) sm[threadIdx.x] += sm[threadIdx.x + off];
        __syncthreads();
    }
    if (threadIdx.x == 0) {
        g_lossPartial[blockIdx.x] = sm[0];
        __threadfence();
        last = (atomicAdd(&g_ctr, 1) == 31);
    }
    __syncthreads();
    if (last && threadIdx.x < 32) {
        __threadfence();
        float v = g_lossPartial[threadIdx.x];
        #pragma unroll
        for (int off = 16; off > 0; off >>= 1)
            v += __shfl_down_sync(0xffffffffu, v, off);
        if (threadIdx.x == 0) { out[0] = v * (LN2 / (float)NN); g_ctr = 0; }
    }
}

// ---------------------------------------------------------------------------
extern "C" void kernel_launch(void* const* d_in, const int* in_sizes, int n_in,
                              void* d_out, int out_size)
{
    (void)in_sizes; (void)n_in; (void)out_size;
    const float* z1 = (const float*)d_in[0];
    const float* z2 = (const float*)d_in[1];
    float* out = (float*)d_out;

    static int smem_set = 0;
    const int SMEM_BYTES = 98304;          // A 64KB + B 32KB -> 2 CTAs/SM
    if (!smem_set) {
        cudaFuncSetAttribute(sim_mma_kernel,
                             cudaFuncAttributeMaxDynamicSharedMemorySize, SMEM_BYTES);
        smem_set = 1;
    }

    normalize_kernel<<<NN / 8, 256>>>(z1, z2);
    sim_mma_kernel<<<NRUN, 256, SMEM_BYTES>>>();
    loss_reduce_kernel<<<32, 256>>>(out);
}